// round 13
// baseline (speedup 1.0000x reference)
#include <cuda_runtime.h>

#define Hn 512
#define Wn 512
#define Bn 32
#define EPSf 1e-7f
#define DTf 0.05f

__device__ float g_partial[1024];

__device__ __forceinline__ float frcp(float x) {
    float r; asm("rcp.approx.ftz.f32 %0, %1;" : "=f"(r) : "f"(x)); return r;
}
__device__ __forceinline__ float frsq(float x) {
    float r; asm("rsqrt.approx.ftz.f32 %0, %1;" : "=f"(r) : "f"(x)); return r;
}

// ---------------- Pass 1: partial max of e = ((sobel_x)^2+(sobel_y)^2)^2 ----
__global__ __launch_bounds__(256) void reduce_max_kernel(const float* __restrict__ img) {
    const int lane = threadIdx.x;
    const int x0 = blockIdx.x * 128 + lane * 4;
    const int yb = (blockIdx.y * 8 + threadIdx.y) * 8;
    const float* p = img + (size_t)blockIdx.z * Hn * Wn;

    float w0[6], w1[6], w2[6];
    auto ldr = [&](int y, float* w) {
        bool ok = ((unsigned)y < (unsigned)Hn);
        const float* r = p + (size_t)y * Wn + x0;
        float4 f = make_float4(0.f, 0.f, 0.f, 0.f);
        if (ok) f = *(const float4*)r;
        w[1] = f.x; w[2] = f.y; w[3] = f.z; w[4] = f.w;
        w[0] = (ok && x0 >= 1) ? r[-1] : 0.f;
        w[5] = (ok && x0 + 4 < Wn) ? r[4] : 0.f;
    };

    ldr(yb - 1, w0);
    ldr(yb, w1);
    float m = 0.f;
    #pragma unroll
    for (int k = 0; k < 8; ++k) {
        ldr(yb + k + 1, w2);
        #pragma unroll
        for (int j = 0; j < 4; ++j) {
            float sx = (w0[j] - w0[j+2]) + 2.f * (w1[j] - w1[j+2]) + (w2[j] - w2[j+2]);
            float sy = (w0[j] - w2[j]) + 2.f * (w0[j+1] - w2[j+1]) + (w0[j+2] - w2[j+2]);
            float s = sx * sx + sy * sy;
            m = fmaxf(m, s * s);
        }
        #pragma unroll
        for (int q = 0; q < 6; ++q) { w0[q] = w1[q]; w1[q] = w2[q]; }
    }

    #pragma unroll
    for (int o = 16; o > 0; o >>= 1)
        m = fmaxf(m, __shfl_xor_sync(0xffffffffu, m, o));
    __shared__ float wmax[8];
    if (lane == 0) wmax[threadIdx.y] = m;
    __syncthreads();
    if (threadIdx.y == 0 && lane == 0) {
        float v = wmax[0];
        #pragma unroll
        for (int i = 1; i < 8; ++i) v = fmaxf(v, wmax[i]);
        int bid = ((int)blockIdx.z * 8 + blockIdx.y) * 4 + blockIdx.x;
        g_partial[bid] = v;
    }
}

// ---------------- Pass 2: register-rolling fused forcing ---------------------
struct W8 { float v[8]; };
struct I6 { float e[6]; float p[6]; float q[4]; };

// 8-wide window: cols c0-2 .. c0+5, via aligned float4 + two predicated float2.
__device__ __forceinline__ W8 load_row8(const float* __restrict__ base, int y, int c0) {
    W8 w;
    const bool rok = ((unsigned)y < (unsigned)Hn);
    const float* r = base + (size_t)y * Wn + c0;
    float4 f = make_float4(0.f, 0.f, 0.f, 0.f);
    if (rok) f = *(const float4*)r;
    float2 l = make_float2(0.f, 0.f), rr = make_float2(0.f, 0.f);
    if (rok && c0 >= 2)       l  = *(const float2*)(r - 2);
    if (rok && c0 + 5 < Wn)   rr = *(const float2*)(r + 4);
    w.v[0] = l.x; w.v[1] = l.y;
    w.v[2] = f.x; w.v[3] = f.y; w.v[4] = f.z; w.v[5] = f.w;
    w.v[6] = rr.x; w.v[7] = rr.y;
    return w;
}

// intermediates (edges, px, py) at row y, cols c0-1 .. c0+4 (6-wide; py center 4)
__device__ __forceinline__ I6 intermed(const W8& im, const W8& ic, const W8& ip,
                                       const W8& um, const W8& uc, const W8& up,
                                       int y, int c0, float maxv) {
    I6 o;
    bool rok = ((unsigned)y < (unsigned)Hn);
    #pragma unroll
    for (int j = 0; j < 6; ++j) {
        float sx = (im.v[j] - im.v[j+2]) + 2.f * (ic.v[j] - ic.v[j+2]) + (ip.v[j] - ip.v[j+2]);
        float sy = (im.v[j] - ip.v[j]) + 2.f * (im.v[j+1] - ip.v[j+1]) + (im.v[j+2] - ip.v[j+2]);
        float s = sx * sx + sy * sy;
        float e = s * s;
        float edges = maxv * frcp(e + maxv);          // == 1/(e/maxv + 1)
        float gux = uc.v[j+2] - uc.v[j];
        float guy = um.v[j+1] - up.v[j+1];
        float qq = gux * gux + guy * guy + EPSf;
        float rs = frsq(qq);                           // ~ 1/(sqrt(qq)+EPS)
        int cc = c0 - 1 + j;
        bool ok = rok && ((unsigned)cc < (unsigned)Wn);
        o.e[j] = ok ? edges : 0.f;
        o.p[j] = ok ? gux * rs : 0.f;
        if (j >= 1 && j <= 4) o.q[j - 1] = ok ? guy * rs : 0.f;
    }
    return o;
}

#define STEP_BODY(mI, cI, pI, mU, cU, pU, Ea, Eb, Ecv, rr)                     \
        Ecv = intermed(mI, cI, pI, mU, cU, pU, (rr), c0, maxv);                 \
        {                                                                       \
            int ey = (rr) - 1;                                                  \
            float rr4[4];                                                       \
            _Pragma("unroll")                                                   \
            for (int i = 0; i < 4; ++i) {                                       \
                float u_c = mU.v[i+2];                                          \
                float uxm = mU.v[i+1];                                          \
                float uxp = mU.v[i+3];                                          \
                float uyp = st[i];          /* row ey-1 */                      \
                float uym = cU.v[i+2];      /* row ey+1 */                      \
                float xp = uxp - u_c;                                           \
                float xn = u_c - uxm;                                           \
                float yp = uyp - u_c;                                           \
                float yn = u_c - uym;                                           \
                float gux = uxp - uxm;                                          \
                float guy = uyp - uym;                                          \
                float qq = gux * gux + guy * guy + EPSf;                        \
                float rs = frsq(qq);                                            \
                float normu = qq * rs;                                          \
                float gex = Eb.e[i+2] - Eb.e[i];                                \
                float gey = Ea.e[i+1] - Ecv.e[i+1];                             \
                float edges_c = Eb.e[i+1];                                      \
                float kappa = (Eb.p[i+2] - Eb.p[i]) + (Ea.q[i] - Ecv.q[i]);     \
                float fxp = fmaxf(gex, 0.f);                                    \
                float fxn = fminf(gex, 0.f);                                    \
                float fyp = fmaxf(gey, 0.f);                                    \
                float fyn = fminf(gey, 0.f);                                    \
                float tr = (fxp*xp + fxn*xn) + (fyp*yp + fyn*yn);               \
                float balloon = edges_c * normu;                                \
                rr4[i] = u_c + balloon * (kappa * cA + cG) + tr * cB;           \
            }                                                                   \
            *(float4*)(oB + (size_t)ey * Wn + c0) =                             \
                make_float4(rr4[0], rr4[1], rr4[2], rr4[3]);                    \
        }

#define STEP(mI, cI, pI, mU, cU, pU, Ea, Eb, Ecv, rr)                          \
    do {                                                                        \
        STEP_BODY(mI, cI, pI, mU, cU, pU, Ea, Eb, Ecv, rr)                      \
        st[0] = mU.v[2]; st[1] = mU.v[3]; st[2] = mU.v[4]; st[3] = mU.v[5];     \
        mI = load_row8(pi, (rr) + 2, c0);                                       \
        mU = load_row8(pu, (rr) + 2, c0);                                       \
    } while (0)

// final step: no trailing loads (rows beyond the strip are never used)
#define STEP_LAST(mI, cI, pI, mU, cU, pU, Ea, Eb, Ecv, rr)                     \
    do {                                                                        \
        STEP_BODY(mI, cI, pI, mU, cU, pU, Ea, Eb, Ecv, rr)                      \
    } while (0)

// 128-thread blocks (4 warps); warp task = 16-row x 128-col strip. grid = 1024.
__global__ __launch_bounds__(128) void forcing_kernel(
    const float* __restrict__ u,
    const float* __restrict__ img,
    const float* __restrict__ alpha_p,
    const float* __restrict__ beta_p,
    const float* __restrict__ gamma_p,
    float* __restrict__ out)
{
    const int tid = threadIdx.x;
    const int lane = tid & 31;
    const int wrp  = tid >> 5;

    // prologue: block-wide reduction of 1024 partial maxima (8 per thread)
    __shared__ float s_red[4];
    {
        float4 f0 = *(const float4*)&g_partial[tid * 8];
        float4 f1 = *(const float4*)&g_partial[tid * 8 + 4];
        float v = fmaxf(fmaxf(fmaxf(f0.x, f0.y), fmaxf(f0.z, f0.w)),
                        fmaxf(fmaxf(f1.x, f1.y), fmaxf(f1.z, f1.w)));
        #pragma unroll
        for (int o = 16; o > 0; o >>= 1)
            v = fmaxf(v, __shfl_xor_sync(0xffffffffu, v, o));
        if (lane == 0) s_red[wrp] = v;
        __syncthreads();
    }
    const float maxv = fmaxf(fmaxf(s_red[0], s_red[1]), fmaxf(s_red[2], s_red[3]));

    const int ww  = blockIdx.x * 4 + wrp;  // 0..4095 warp tasks
    const int bb  = ww >> 7;               // batch (128 tasks per image)
    const int rem = ww & 127;
    const int ys  = (rem >> 2) * 16;       // segment start row (32 segments)
    const int c0  = (rem & 3) * 128 + lane * 4;

    const float* pu = u   + (size_t)bb * Hn * Wn;
    const float* pi = img + (size_t)bb * Hn * Wn;
    float* oB = out + (size_t)bb * Hn * Wn;

    const float cA = DTf * alpha_p[0];          // DT*alpha
    const float cB = 20.f * DTf * beta_p[0];    // 20*DT*beta
    const float cG = DTf * gamma_p[0];          // DT*gamma

    // ---- priming ----
    W8 t_m2 = load_row8(pi, ys - 2, c0);
    W8 t_m1 = load_row8(pi, ys - 1, c0);
    W8 t_0  = load_row8(pi, ys,     c0);
    W8 s_m2 = load_row8(pu, ys - 2, c0);
    W8 s_m1 = load_row8(pu, ys - 1, c0);
    W8 s_0  = load_row8(pu, ys,     c0);
    I6 Ia = intermed(t_m2, t_m1, t_0, s_m2, s_m1, s_0, ys - 1, c0, maxv);
    W8 t_1 = load_row8(pi, ys + 1, c0);
    W8 s_1 = load_row8(pu, ys + 1, c0);
    I6 Ib = intermed(t_m1, t_0, t_1, s_m1, s_0, s_1, ys, c0, maxv);
    W8 t_2 = load_row8(pi, ys + 2, c0);
    W8 s_2 = load_row8(pu, ys + 2, c0);

    float st[4] = { s_m1.v[2], s_m1.v[3], s_m1.v[4], s_m1.v[5] };

    W8 imA = t_0, imB = t_1, imC = t_2;
    W8 uwA = s_0, uwB = s_1, uwC = s_2;
    I6 Ic;

    // 16 steps: 5 triples + 1 (emit rows ys .. ys+15)
    int r = ys + 1;
    #pragma unroll 1
    for (int it = 0; it < 5; ++it) {
        STEP(imA, imB, imC, uwA, uwB, uwC, Ia, Ib, Ic, r);
        STEP(imB, imC, imA, uwB, uwC, uwA, Ib, Ic, Ia, r + 1);
        STEP(imC, imA, imB, uwC, uwA, uwB, Ic, Ia, Ib, r + 2);
        r += 3;
    }
    STEP_LAST(imA, imB, imC, uwA, uwB, uwC, Ia, Ib, Ic, r);
}

extern "C" void kernel_launch(void* const* d_in, const int* in_sizes, int n_in,
                              void* d_out, int out_size) {
    const float* u     = (const float*)d_in[0];
    const float* img   = (const float*)d_in[1];
    const float* alpha = (const float*)d_in[2];
    const float* beta  = (const float*)d_in[3];
    const float* gamma = (const float*)d_in[4];
    float* out = (float*)d_out;

    dim3 rblk(32, 8, 1);
    dim3 rgrd(4, 8, Bn);
    reduce_max_kernel<<<rgrd, rblk>>>(img);

    forcing_kernel<<<1024, 128>>>(u, img, alpha, beta, gamma, out);
}

// round 14
// speedup vs baseline: 1.0860x; 1.0860x over previous
#include <cuda_runtime.h>

#define Hn 512
#define Wn 512
#define Bn 32
#define EPSf 1e-7f
#define DTf 0.05f

__device__ float g_partial[1024];

__device__ __forceinline__ float frcp(float x) {
    float r; asm("rcp.approx.ftz.f32 %0, %1;" : "=f"(r) : "f"(x)); return r;
}
__device__ __forceinline__ float frsq(float x) {
    float r; asm("rsqrt.approx.ftz.f32 %0, %1;" : "=f"(r) : "f"(x)); return r;
}

// ---------------- Pass 1: partial max of e = ((sobel_x)^2+(sobel_y)^2)^2 ----
__global__ __launch_bounds__(256) void reduce_max_kernel(const float* __restrict__ img) {
    const int lane = threadIdx.x;
    const int x0 = blockIdx.x * 128 + lane * 4;
    const int yb = (blockIdx.y * 8 + threadIdx.y) * 8;
    const float* p = img + (size_t)blockIdx.z * Hn * Wn;

    float w0[6], w1[6], w2[6];
    auto ldr = [&](int y, float* w) {
        bool ok = ((unsigned)y < (unsigned)Hn);
        const float* r = p + (size_t)y * Wn + x0;
        float4 f = make_float4(0.f, 0.f, 0.f, 0.f);
        if (ok) f = *(const float4*)r;
        w[1] = f.x; w[2] = f.y; w[3] = f.z; w[4] = f.w;
        w[0] = (ok && x0 >= 1) ? r[-1] : 0.f;
        w[5] = (ok && x0 + 4 < Wn) ? r[4] : 0.f;
    };

    ldr(yb - 1, w0);
    ldr(yb, w1);
    float m = 0.f;
    #pragma unroll
    for (int k = 0; k < 8; ++k) {
        ldr(yb + k + 1, w2);
        #pragma unroll
        for (int j = 0; j < 4; ++j) {
            float sx = (w0[j] - w0[j+2]) + 2.f * (w1[j] - w1[j+2]) + (w2[j] - w2[j+2]);
            float sy = (w0[j] - w2[j]) + 2.f * (w0[j+1] - w2[j+1]) + (w0[j+2] - w2[j+2]);
            float s = sx * sx + sy * sy;
            m = fmaxf(m, s * s);
        }
        #pragma unroll
        for (int q = 0; q < 6; ++q) { w0[q] = w1[q]; w1[q] = w2[q]; }
    }

    #pragma unroll
    for (int o = 16; o > 0; o >>= 1)
        m = fmaxf(m, __shfl_xor_sync(0xffffffffu, m, o));
    __shared__ float wmax[8];
    if (lane == 0) wmax[threadIdx.y] = m;
    __syncthreads();
    if (threadIdx.y == 0 && lane == 0) {
        float v = wmax[0];
        #pragma unroll
        for (int i = 1; i < 8; ++i) v = fmaxf(v, wmax[i]);
        int bid = ((int)blockIdx.z * 8 + blockIdx.y) * 4 + blockIdx.x;
        g_partial[bid] = v;
    }
    // allow the dependent forcing kernel to begin its prologue
    cudaTriggerProgrammaticLaunchCompletion();
}

// ---------------- Pass 2: register-rolling fused forcing ---------------------
struct W8 { float v[8]; };
struct I6 { float e[6]; float p[6]; float q[4]; };

// 8-wide window: cols c0-2 .. c0+5, via aligned float4 + two predicated float2.
__device__ __forceinline__ W8 load_row8(const float* __restrict__ base, int y, int c0) {
    W8 w;
    const bool rok = ((unsigned)y < (unsigned)Hn);
    const float* r = base + (size_t)y * Wn + c0;
    float4 f = make_float4(0.f, 0.f, 0.f, 0.f);
    if (rok) f = *(const float4*)r;
    float2 l = make_float2(0.f, 0.f), rr = make_float2(0.f, 0.f);
    if (rok && c0 >= 2)       l  = *(const float2*)(r - 2);
    if (rok && c0 + 5 < Wn)   rr = *(const float2*)(r + 4);
    w.v[0] = l.x; w.v[1] = l.y;
    w.v[2] = f.x; w.v[3] = f.y; w.v[4] = f.z; w.v[5] = f.w;
    w.v[6] = rr.x; w.v[7] = rr.y;
    return w;
}

// intermediates (edges, px, py) at row y, cols c0-1 .. c0+4 (6-wide; py center 4)
__device__ __forceinline__ I6 intermed(const W8& im, const W8& ic, const W8& ip,
                                       const W8& um, const W8& uc, const W8& up,
                                       int y, int c0, float maxv) {
    I6 o;
    bool rok = ((unsigned)y < (unsigned)Hn);
    #pragma unroll
    for (int j = 0; j < 6; ++j) {
        float sx = (im.v[j] - im.v[j+2]) + 2.f * (ic.v[j] - ic.v[j+2]) + (ip.v[j] - ip.v[j+2]);
        float sy = (im.v[j] - ip.v[j]) + 2.f * (im.v[j+1] - ip.v[j+1]) + (im.v[j+2] - ip.v[j+2]);
        float s = sx * sx + sy * sy;
        float e = s * s;
        float edges = maxv * frcp(e + maxv);          // == 1/(e/maxv + 1)
        float gux = uc.v[j+2] - uc.v[j];
        float guy = um.v[j+1] - up.v[j+1];
        float qq = gux * gux + guy * guy + EPSf;
        float rs = frsq(qq);                           // ~ 1/(sqrt(qq)+EPS)
        int cc = c0 - 1 + j;
        bool ok = rok && ((unsigned)cc < (unsigned)Wn);
        o.e[j] = ok ? edges : 0.f;
        o.p[j] = ok ? gux * rs : 0.f;
        if (j >= 1 && j <= 4) o.q[j - 1] = ok ? guy * rs : 0.f;
    }
    return o;
}

#define STEP_BODY(mI, cI, pI, mU, cU, pU, Ea, Eb, Ecv, rr)                     \
        Ecv = intermed(mI, cI, pI, mU, cU, pU, (rr), c0, maxv);                 \
        {                                                                       \
            int ey = (rr) - 1;                                                  \
            float rr4[4];                                                       \
            _Pragma("unroll")                                                   \
            for (int i = 0; i < 4; ++i) {                                       \
                float u_c = mU.v[i+2];                                          \
                float uxm = mU.v[i+1];                                          \
                float uxp = mU.v[i+3];                                          \
                float uyp = st[i];          /* row ey-1 */                      \
                float uym = cU.v[i+2];      /* row ey+1 */                      \
                float xp = uxp - u_c;                                           \
                float xn = u_c - uxm;                                           \
                float yp = uyp - u_c;                                           \
                float yn = u_c - uym;                                           \
                float gux = uxp - uxm;                                          \
                float guy = uyp - uym;                                          \
                float qq = gux * gux + guy * guy + EPSf;                        \
                float rs = frsq(qq);                                            \
                float normu = qq * rs;                                          \
                float gex = Eb.e[i+2] - Eb.e[i];                                \
                float gey = Ea.e[i+1] - Ecv.e[i+1];                             \
                float edges_c = Eb.e[i+1];                                      \
                float kappa = (Eb.p[i+2] - Eb.p[i]) + (Ea.q[i] - Ecv.q[i]);     \
                float fxp = fmaxf(gex, 0.f);                                    \
                float fxn = fminf(gex, 0.f);                                    \
                float fyp = fmaxf(gey, 0.f);                                    \
                float fyn = fminf(gey, 0.f);                                    \
                float transport = 20.f * ((fxp*xp + fxn*xn) + (fyp*yp + fyn*yn));\
                float curvature = edges_c * kappa * normu;                      \
                float balloon   = edges_c * normu;                              \
                rr4[i] = u_c + DTf * (curvature*a + transport*be + balloon*ga); \
            }                                                                   \
            *(float4*)(oB + (size_t)ey * Wn + c0) =                             \
                make_float4(rr4[0], rr4[1], rr4[2], rr4[3]);                    \
        }

#define STEP(mI, cI, pI, mU, cU, pU, Ea, Eb, Ecv, rr)                          \
    do {                                                                        \
        STEP_BODY(mI, cI, pI, mU, cU, pU, Ea, Eb, Ecv, rr)                      \
        st[0] = mU.v[2]; st[1] = mU.v[3]; st[2] = mU.v[4]; st[3] = mU.v[5];     \
        mI = load_row8(pi, (rr) + 2, c0);                                       \
        mU = load_row8(pu, (rr) + 2, c0);                                       \
    } while (0)

#define STEP_LAST(mI, cI, pI, mU, cU, pU, Ea, Eb, Ecv, rr)                     \
    do {                                                                        \
        STEP_BODY(mI, cI, pI, mU, cU, pU, Ea, Eb, Ecv, rr)                      \
    } while (0)

// 128-thread blocks (4 warps); warp task = 16-row x 128-col strip. grid = 1024.
__global__ __launch_bounds__(128) void forcing_kernel(
    const float* __restrict__ u,
    const float* __restrict__ img,
    const float* __restrict__ alpha_p,
    const float* __restrict__ beta_p,
    const float* __restrict__ gamma_p,
    float* __restrict__ out)
{
    const int tid = threadIdx.x;
    const int lane = tid & 31;
    const int wrp  = tid >> 5;

    const int ww  = blockIdx.x * 4 + wrp;  // 0..4095 warp tasks
    const int bb  = ww >> 7;               // batch (128 tasks per image)
    const int rem = ww & 127;
    const int ys  = (rem >> 2) * 16;       // segment start row (32 segments)
    const int c0  = (rem & 3) * 128 + lane * 4;

    const float* pu = u   + (size_t)bb * Hn * Wn;
    const float* pi = img + (size_t)bb * Hn * Wn;
    float* oB = out + (size_t)bb * Hn * Wn;

    // ---- priming loads (independent of reduce's output) — issue BEFORE the
    //      grid-dependency sync so they overlap the producer kernel's tail ----
    W8 t_m2 = load_row8(pi, ys - 2, c0);
    W8 t_m1 = load_row8(pi, ys - 1, c0);
    W8 t_0  = load_row8(pi, ys,     c0);
    W8 s_m2 = load_row8(pu, ys - 2, c0);
    W8 s_m1 = load_row8(pu, ys - 1, c0);
    W8 s_0  = load_row8(pu, ys,     c0);
    W8 t_1 = load_row8(pi, ys + 1, c0);
    W8 s_1 = load_row8(pu, ys + 1, c0);
    W8 t_2 = load_row8(pi, ys + 2, c0);
    W8 s_2 = load_row8(pu, ys + 2, c0);

    const float a  = alpha_p[0];
    const float be = beta_p[0];
    const float ga = gamma_p[0];

    // ---- wait for reduce_max_kernel's g_partial writes ----
    cudaGridDependencySynchronize();

    // block-wide reduction of 1024 partial maxima (8 per thread)
    __shared__ float s_red[4];
    {
        float4 f0 = *(const float4*)&g_partial[tid * 8];
        float4 f1 = *(const float4*)&g_partial[tid * 8 + 4];
        float v = fmaxf(fmaxf(fmaxf(f0.x, f0.y), fmaxf(f0.z, f0.w)),
                        fmaxf(fmaxf(f1.x, f1.y), fmaxf(f1.z, f1.w)));
        #pragma unroll
        for (int o = 16; o > 0; o >>= 1)
            v = fmaxf(v, __shfl_xor_sync(0xffffffffu, v, o));
        if (lane == 0) s_red[wrp] = v;
        __syncthreads();
    }
    const float maxv = fmaxf(fmaxf(s_red[0], s_red[1]), fmaxf(s_red[2], s_red[3]));

    // ---- priming intermediates ----
    I6 Ia = intermed(t_m2, t_m1, t_0, s_m2, s_m1, s_0, ys - 1, c0, maxv);
    I6 Ib = intermed(t_m1, t_0, t_1, s_m1, s_0, s_1, ys, c0, maxv);

    float st[4] = { s_m1.v[2], s_m1.v[3], s_m1.v[4], s_m1.v[5] };

    W8 imA = t_0, imB = t_1, imC = t_2;
    W8 uwA = s_0, uwB = s_1, uwC = s_2;
    I6 Ic;

    // 16 steps: 5 triples + 1 (emit rows ys .. ys+15)
    int r = ys + 1;
    #pragma unroll 1
    for (int it = 0; it < 5; ++it) {
        STEP(imA, imB, imC, uwA, uwB, uwC, Ia, Ib, Ic, r);
        STEP(imB, imC, imA, uwB, uwC, uwA, Ib, Ic, Ia, r + 1);
        STEP(imC, imA, imB, uwC, uwA, uwB, Ic, Ia, Ib, r + 2);
        r += 3;
    }
    STEP_LAST(imA, imB, imC, uwA, uwB, uwC, Ia, Ib, Ic, r);
}

extern "C" void kernel_launch(void* const* d_in, const int* in_sizes, int n_in,
                              void* d_out, int out_size) {
    const float* u     = (const float*)d_in[0];
    const float* img   = (const float*)d_in[1];
    const float* alpha = (const float*)d_in[2];
    const float* beta  = (const float*)d_in[3];
    const float* gamma = (const float*)d_in[4];
    float* out = (float*)d_out;

    dim3 rblk(32, 8, 1);
    dim3 rgrd(4, 8, Bn);
    reduce_max_kernel<<<rgrd, rblk>>>(img);

    // forcing with Programmatic Dependent Launch: overlaps its prologue
    // (index setup + priming loads of u/img) with reduce's tail.
    cudaLaunchConfig_t cfg = {};
    cfg.gridDim = dim3(1024, 1, 1);
    cfg.blockDim = dim3(128, 1, 1);
    cfg.dynamicSmemBytes = 0;
    cfg.stream = 0;  // legacy default stream (inherits graph capture)
    cudaLaunchAttribute attrs[1];
    attrs[0].id = cudaLaunchAttributeProgrammaticStreamSerialization;
    attrs[0].val.programmaticStreamSerializationAllowed = 1;
    cfg.attrs = attrs;
    cfg.numAttrs = 1;
    cudaLaunchKernelEx(&cfg, forcing_kernel, u, img, alpha, beta, gamma, out);
}

// round 15
// speedup vs baseline: 1.0869x; 1.0008x over previous
#include <cuda_runtime.h>

#define Hn 512
#define Wn 512
#define Bn 32
#define EPSf 1e-7f
#define DTf 0.05f

__device__ float g_partial[1024];

__device__ __forceinline__ float frcp(float x) {
    float r; asm("rcp.approx.ftz.f32 %0, %1;" : "=f"(r) : "f"(x)); return r;
}
__device__ __forceinline__ float frsq(float x) {
    float r; asm("rsqrt.approx.ftz.f32 %0, %1;" : "=f"(r) : "f"(x)); return r;
}

// ---------------- Pass 1: partial max of e = ((sobel_x)^2+(sobel_y)^2)^2 ----
__global__ __launch_bounds__(256) void reduce_max_kernel(const float* __restrict__ img) {
    const int lane = threadIdx.x;
    const int x0 = blockIdx.x * 128 + lane * 4;
    const int yb = (blockIdx.y * 8 + threadIdx.y) * 8;
    const float* p = img + (size_t)blockIdx.z * Hn * Wn;

    float w0[6], w1[6], w2[6];
    auto ldr = [&](int y, float* w) {
        bool ok = ((unsigned)y < (unsigned)Hn);
        const float* r = p + (size_t)y * Wn + x0;
        float4 f = make_float4(0.f, 0.f, 0.f, 0.f);
        if (ok) f = *(const float4*)r;
        w[1] = f.x; w[2] = f.y; w[3] = f.z; w[4] = f.w;
        w[0] = (ok && x0 >= 1) ? r[-1] : 0.f;
        w[5] = (ok && x0 + 4 < Wn) ? r[4] : 0.f;
    };

    ldr(yb - 1, w0);
    ldr(yb, w1);
    float m = 0.f;
    #pragma unroll
    for (int k = 0; k < 8; ++k) {
        ldr(yb + k + 1, w2);
        #pragma unroll
        for (int j = 0; j < 4; ++j) {
            float sx = (w0[j] - w0[j+2]) + 2.f * (w1[j] - w1[j+2]) + (w2[j] - w2[j+2]);
            float sy = (w0[j] - w2[j]) + 2.f * (w0[j+1] - w2[j+1]) + (w0[j+2] - w2[j+2]);
            float s = sx * sx + sy * sy;
            m = fmaxf(m, s * s);
        }
        #pragma unroll
        for (int q = 0; q < 6; ++q) { w0[q] = w1[q]; w1[q] = w2[q]; }
    }

    #pragma unroll
    for (int o = 16; o > 0; o >>= 1)
        m = fmaxf(m, __shfl_xor_sync(0xffffffffu, m, o));
    __shared__ float wmax[8];
    if (lane == 0) wmax[threadIdx.y] = m;
    __syncthreads();
    if (threadIdx.y == 0 && lane == 0) {
        float v = wmax[0];
        #pragma unroll
        for (int i = 1; i < 8; ++i) v = fmaxf(v, wmax[i]);
        int bid = ((int)blockIdx.z * 8 + blockIdx.y) * 4 + blockIdx.x;
        g_partial[bid] = v;
    }
    cudaTriggerProgrammaticLaunchCompletion();
}

// ---------------- Pass 2: register-rolling fused forcing ---------------------
struct W8 { float v[8]; };
// e[] holds UNSCALED re = rcp(e_raw + maxv); true edges = maxv * re
// (maxv is folded into cA/cB/cG — output is linear in maxv through all terms).
struct I6 { float e[6]; float p[6]; float q[4]; };

__device__ __forceinline__ W8 load_row8(const float* __restrict__ base, int y, int c0) {
    W8 w;
    const bool rok = ((unsigned)y < (unsigned)Hn);
    const float* r = base + (size_t)y * Wn + c0;
    float4 f = make_float4(0.f, 0.f, 0.f, 0.f);
    if (rok) f = *(const float4*)r;
    float2 l = make_float2(0.f, 0.f), rr = make_float2(0.f, 0.f);
    if (rok && c0 >= 2)       l  = *(const float2*)(r - 2);
    if (rok && c0 + 5 < Wn)   rr = *(const float2*)(r + 4);
    w.v[0] = l.x; w.v[1] = l.y;
    w.v[2] = f.x; w.v[3] = f.y; w.v[4] = f.z; w.v[5] = f.w;
    w.v[6] = rr.x; w.v[7] = rr.y;
    return w;
}

// intermediates at row y, cols c0-1 .. c0+4 (6-wide; py center 4).
// x-guards are static per j: only j=0 (c0>0) and j=5 (c0<508) can be OOB.
__device__ __forceinline__ I6 intermed(const W8& im, const W8& ic, const W8& ip,
                                       const W8& um, const W8& uc, const W8& up,
                                       int y, int c0, float maxv) {
    I6 o;
    bool rok = ((unsigned)y < (unsigned)Hn);
    #pragma unroll
    for (int j = 0; j < 6; ++j) {
        float sx = (im.v[j] - im.v[j+2]) + 2.f * (ic.v[j] - ic.v[j+2]) + (ip.v[j] - ip.v[j+2]);
        float sy = (im.v[j] - ip.v[j]) + 2.f * (im.v[j+1] - ip.v[j+1]) + (im.v[j+2] - ip.v[j+2]);
        float s = sx * sx + sy * sy;
        float e = s * s;
        float re = frcp(e + maxv);                    // unscaled edges
        float gux = uc.v[j+2] - uc.v[j];
        float guy = um.v[j+1] - up.v[j+1];
        float qq = gux * gux + guy * guy + EPSf;
        float rs = frsq(qq);                           // ~ 1/(sqrt(qq)+EPS)
        bool ok = rok;
        if (j == 0) ok = rok && (c0 > 0);
        if (j == 5) ok = rok && (c0 < 508);
        o.e[j] = ok ? re : 0.f;
        o.p[j] = ok ? gux * rs : 0.f;
        if (j >= 1 && j <= 4) o.q[j - 1] = ok ? guy * rs : 0.f;
    }
    return o;
}

#define STEP_BODY(mI, cI, pI, mU, cU, pU, Ea, Eb, Ecv, rr)                     \
        Ecv = intermed(mI, cI, pI, mU, cU, pU, (rr), c0, maxv);                 \
        {                                                                       \
            int ey = (rr) - 1;                                                  \
            float rr4[4];                                                       \
            _Pragma("unroll")                                                   \
            for (int i = 0; i < 4; ++i) {                                       \
                float u_c = mU.v[i+2];                                          \
                float uxm = mU.v[i+1];                                          \
                float uxp = mU.v[i+3];                                          \
                float uyp = st[i];          /* row ey-1 */                      \
                float uym = cU.v[i+2];      /* row ey+1 */                      \
                float xp = uxp - u_c;                                           \
                float xn = u_c - uxm;                                           \
                float yp = uyp - u_c;                                           \
                float yn = u_c - uym;                                           \
                float gux = uxp - uxm;                                          \
                float guy = uyp - uym;                                          \
                float qq = gux * gux + guy * guy + EPSf;                        \
                float rs = frsq(qq);                                            \
                float normu = qq * rs;                                          \
                float gex = Eb.e[i+2] - Eb.e[i];        /* unscaled */          \
                float gey = Ea.e[i+1] - Ecv.e[i+1];     /* unscaled */          \
                float edges_c = Eb.e[i+1];              /* unscaled */          \
                float kappa = (Eb.p[i+2] - Eb.p[i]) + (Ea.q[i] - Ecv.q[i]);     \
                float selx = (gex > 0.f) ? xp : xn;                             \
                float sely = (gey > 0.f) ? yp : yn;                             \
                float tr = gex * selx + gey * sely;     /* == upwind sum */     \
                float balloon = edges_c * normu;                                \
                rr4[i] = u_c + balloon * (kappa * cA + cG) + tr * cB;           \
            }                                                                   \
            *(float4*)(oB + (size_t)ey * Wn + c0) =                             \
                make_float4(rr4[0], rr4[1], rr4[2], rr4[3]);                    \
        }

#define STEP(mI, cI, pI, mU, cU, pU, Ea, Eb, Ecv, rr)                          \
    do {                                                                        \
        STEP_BODY(mI, cI, pI, mU, cU, pU, Ea, Eb, Ecv, rr)                      \
        st[0] = mU.v[2]; st[1] = mU.v[3]; st[2] = mU.v[4]; st[3] = mU.v[5];     \
        mI = load_row8(pi, (rr) + 2, c0);                                       \
        mU = load_row8(pu, (rr) + 2, c0);                                       \
    } while (0)

#define STEP_LAST(mI, cI, pI, mU, cU, pU, Ea, Eb, Ecv, rr)                     \
    do {                                                                        \
        STEP_BODY(mI, cI, pI, mU, cU, pU, Ea, Eb, Ecv, rr)                      \
    } while (0)

// 128-thread blocks (4 warps); warp task = 16-row x 128-col strip. grid = 1024.
__global__ __launch_bounds__(128) void forcing_kernel(
    const float* __restrict__ u,
    const float* __restrict__ img,
    const float* __restrict__ alpha_p,
    const float* __restrict__ beta_p,
    const float* __restrict__ gamma_p,
    float* __restrict__ out)
{
    const int tid = threadIdx.x;
    const int lane = tid & 31;
    const int wrp  = tid >> 5;

    const int ww  = blockIdx.x * 4 + wrp;  // 0..4095 warp tasks
    const int bb  = ww >> 7;               // batch (128 tasks per image)
    const int rem = ww & 127;
    const int ys  = (rem >> 2) * 16;       // segment start row (32 segments)
    const int c0  = (rem & 3) * 128 + lane * 4;

    const float* pu = u   + (size_t)bb * Hn * Wn;
    const float* pi = img + (size_t)bb * Hn * Wn;
    float* oB = out + (size_t)bb * Hn * Wn;

    // ---- priming loads (independent of reduce) — before grid sync ----
    W8 t_m2 = load_row8(pi, ys - 2, c0);
    W8 t_m1 = load_row8(pi, ys - 1, c0);
    W8 t_0  = load_row8(pi, ys,     c0);
    W8 s_m2 = load_row8(pu, ys - 2, c0);
    W8 s_m1 = load_row8(pu, ys - 1, c0);
    W8 s_0  = load_row8(pu, ys,     c0);
    W8 t_1 = load_row8(pi, ys + 1, c0);
    W8 s_1 = load_row8(pu, ys + 1, c0);
    W8 t_2 = load_row8(pi, ys + 2, c0);
    W8 s_2 = load_row8(pu, ys + 2, c0);

    const float a  = alpha_p[0];
    const float be = beta_p[0];
    const float ga = gamma_p[0];

    // ---- wait for reduce_max_kernel's g_partial writes ----
    cudaGridDependencySynchronize();

    // block-wide reduction of 1024 partial maxima (8 per thread)
    __shared__ float s_red[4];
    {
        float4 f0 = *(const float4*)&g_partial[tid * 8];
        float4 f1 = *(const float4*)&g_partial[tid * 8 + 4];
        float v = fmaxf(fmaxf(fmaxf(f0.x, f0.y), fmaxf(f0.z, f0.w)),
                        fmaxf(fmaxf(f1.x, f1.y), fmaxf(f1.z, f1.w)));
        #pragma unroll
        for (int o = 16; o > 0; o >>= 1)
            v = fmaxf(v, __shfl_xor_sync(0xffffffffu, v, o));
        if (lane == 0) s_red[wrp] = v;
        __syncthreads();
    }
    const float maxv = fmaxf(fmaxf(s_red[0], s_red[1]), fmaxf(s_red[2], s_red[3]));

    // maxv folded into the output constants (output is linear in maxv):
    const float cA = DTf * maxv * a;          // multiplies edges*kappa*normu
    const float cB = 20.f * DTf * maxv * be;  // multiplies transport (unscaled)
    const float cG = DTf * maxv * ga;         // multiplies edges*normu

    // ---- priming intermediates ----
    I6 Ia = intermed(t_m2, t_m1, t_0, s_m2, s_m1, s_0, ys - 1, c0, maxv);
    I6 Ib = intermed(t_m1, t_0, t_1, s_m1, s_0, s_1, ys, c0, maxv);

    float st[4] = { s_m1.v[2], s_m1.v[3], s_m1.v[4], s_m1.v[5] };

    W8 imA = t_0, imB = t_1, imC = t_2;
    W8 uwA = s_0, uwB = s_1, uwC = s_2;
    I6 Ic;

    // 16 steps: 5 triples + 1 (emit rows ys .. ys+15)
    int r = ys + 1;
    #pragma unroll 1
    for (int it = 0; it < 5; ++it) {
        STEP(imA, imB, imC, uwA, uwB, uwC, Ia, Ib, Ic, r);
        STEP(imB, imC, imA, uwB, uwC, uwA, Ib, Ic, Ia, r + 1);
        STEP(imC, imA, imB, uwC, uwA, uwB, Ic, Ia, Ib, r + 2);
        r += 3;
    }
    STEP_LAST(imA, imB, imC, uwA, uwB, uwC, Ia, Ib, Ic, r);
}

extern "C" void kernel_launch(void* const* d_in, const int* in_sizes, int n_in,
                              void* d_out, int out_size) {
    const float* u     = (const float*)d_in[0];
    const float* img   = (const float*)d_in[1];
    const float* alpha = (const float*)d_in[2];
    const float* beta  = (const float*)d_in[3];
    const float* gamma = (const float*)d_in[4];
    float* out = (float*)d_out;

    dim3 rblk(32, 8, 1);
    dim3 rgrd(4, 8, Bn);
    reduce_max_kernel<<<rgrd, rblk>>>(img);

    // forcing with Programmatic Dependent Launch
    cudaLaunchConfig_t cfg = {};
    cfg.gridDim = dim3(1024, 1, 1);
    cfg.blockDim = dim3(128, 1, 1);
    cfg.dynamicSmemBytes = 0;
    cfg.stream = 0;
    cudaLaunchAttribute attrs[1];
    attrs[0].id = cudaLaunchAttributeProgrammaticStreamSerialization;
    attrs[0].val.programmaticStreamSerializationAllowed = 1;
    cfg.attrs = attrs;
    cfg.numAttrs = 1;
    cudaLaunchKernelEx(&cfg, forcing_kernel, u, img, alpha, beta, gamma, out);
}